// round 5
// baseline (speedup 1.0000x reference)
#include <cuda_runtime.h>
#include <cuda_bf16.h>
#include <math.h>

#define NN      50000
#define NE      800000
#define F0      64
#define F1      128
#define F2      32
#define CHUNK   49            // ceil(NN / 1024)

// ---------------- scratch (static device globals) ----------------------------
__device__ float g_ax[NN * F0];     // aggregated x
__device__ float g_a1[NN * F1];     // relu(agg(x) @ W1 + b1)
__device__ float g_h2[NN * F2];     // a1 @ W2
__device__ float g_dinv[NN];
__device__ int   g_cnt[NN];         // zero-initialized at load; self-zeroed by k_scan
__device__ int   g_fill[NN];
__device__ int   g_rowptr[NN + 1];
__device__ int   g_colsrc[NE];

// ---------------- CSR build --------------------------------------------------
__global__ void k_count(const int* __restrict__ dst) {
    int e = blockIdx.x * blockDim.x + threadIdx.x;
    if (e < NE) atomicAdd(&g_cnt[dst[e]], 1);
}

// One block, 1024 threads: dinv + full exclusive scan + fill init + cnt reset.
__global__ void __launch_bounds__(1024) k_scan() {
    __shared__ int warpsum[32];
    int t = threadIdx.x;
    int lane = t & 31, wid = t >> 5;
    int beg = t * CHUNK;
    int end = min(beg + CHUNK, NN);

    int sum = 0;
    for (int i = beg; i < end; i++) {
        int v = g_cnt[i];
        sum += v;
        g_dinv[i] = rsqrtf((float)(v + 1));   // +1 self loop
    }

    // inclusive warp scan of per-thread sums
    int incl = sum;
    #pragma unroll
    for (int off = 1; off < 32; off <<= 1) {
        int u = __shfl_up_sync(0xFFFFFFFFu, incl, off);
        if (lane >= off) incl += u;
    }
    if (lane == 31) warpsum[wid] = incl;
    __syncthreads();
    if (wid == 0) {
        int w = warpsum[lane];
        #pragma unroll
        for (int off = 1; off < 32; off <<= 1) {
            int u = __shfl_up_sync(0xFFFFFFFFu, w, off);
            if (lane >= off) w += u;
        }
        warpsum[lane] = w;
    }
    __syncthreads();

    int base = incl - sum;                 // exclusive within warp
    if (wid > 0) base += warpsum[wid - 1]; // + preceding warps

    int run = base;
    for (int i = beg; i < end; i++) {
        int v = g_cnt[i];
        g_rowptr[i] = run;
        g_fill[i] = run;
        run += v;
        g_cnt[i] = 0;                      // reset for next replay
    }
    if (t == 0) g_rowptr[NN] = NE;
}

__global__ void k_scatter(const int* __restrict__ src, const int* __restrict__ dst) {
    int e = blockIdx.x * blockDim.x + threadIdx.x;
    if (e < NE) {
        int pos = atomicAdd(&g_fill[dst[e]], 1);
        g_colsrc[pos] = src[e];
    }
}

// ---------------- Aggregate x (F=64, warp per node, float2 per lane) ---------
__global__ void __launch_bounds__(256) k_aggx(const float* __restrict__ x) {
    int gtid = blockIdx.x * blockDim.x + threadIdx.x;
    int n = gtid >> 5;
    int lane = gtid & 31;
    if (n >= NN) return;

    const float2* X = (const float2*)x;     // row = 32 float2
    float dn = g_dinv[n];
    float2 s = X[n * 32 + lane];
    float ax = dn * s.x, ay = dn * s.y;

    int e = g_rowptr[n], end = g_rowptr[n + 1];
    for (; e + 3 < end; e += 4) {
        int s0 = g_colsrc[e], s1 = g_colsrc[e + 1], s2 = g_colsrc[e + 2], s3 = g_colsrc[e + 3];
        float d0 = g_dinv[s0], d1 = g_dinv[s1], d2 = g_dinv[s2], d3 = g_dinv[s3];
        float2 v0 = X[s0 * 32 + lane], v1 = X[s1 * 32 + lane];
        float2 v2 = X[s2 * 32 + lane], v3 = X[s3 * 32 + lane];
        ax += d0 * v0.x + d1 * v1.x + d2 * v2.x + d3 * v3.x;
        ay += d0 * v0.y + d1 * v1.y + d2 * v2.y + d3 * v3.y;
    }
    for (; e < end; e++) {
        int sc = g_colsrc[e];
        float d = g_dinv[sc];
        float2 v = X[sc * 32 + lane];
        ax += d * v.x; ay += d * v.y;
    }
    float2 o; o.x = dn * ax; o.y = dn * ay;
    ((float2*)g_ax)[n * 32 + lane] = o;
}

// ---------------- GEMM1: a1 = relu(agg_x @ W1 + b1)  (N x 64 @ 64 x 128) ----
__global__ void __launch_bounds__(128) k_gemm1(const float* __restrict__ W1,
                                               const float* __restrict__ b1) {
    __shared__ float sW[F0 * F1];        // 32 KB
    __shared__ float sA[F0 * 36];        // 9 KB, k-major, padded
    int tid = threadIdx.x;
    int n0 = blockIdx.x * 32;

    {
        const float4* Wp = (const float4*)W1;
        float4* Sp = (float4*)sW;
        #pragma unroll
        for (int i = tid; i < F0 * F1 / 4; i += 128) Sp[i] = Wp[i];
    }
    for (int idx = tid; idx < 32 * F0; idx += 128) {
        int j = idx >> 6, k = idx & 63;
        sA[k * 36 + j] = (n0 + j < NN) ? g_ax[(n0 + j) * F0 + k] : 0.f;
    }
    __syncthreads();

    int cg = tid & 15, jg = tid >> 4;
    int c0 = cg * 8, j0 = jg * 4;

    float acc[4][8];
    #pragma unroll
    for (int a = 0; a < 4; a++)
        #pragma unroll
        for (int b = 0; b < 8; b++) acc[a][b] = 0.f;

    #pragma unroll 4
    for (int k = 0; k < F0; k++) {
        float4 w0 = *(const float4*)&sW[k * F1 + c0];
        float4 w1 = *(const float4*)&sW[k * F1 + c0 + 4];
        float4 av = *(const float4*)&sA[k * 36 + j0];
        float a0 = av.x, a1 = av.y, a2 = av.z, a3 = av.w;
        acc[0][0] = fmaf(a0, w0.x, acc[0][0]); acc[0][1] = fmaf(a0, w0.y, acc[0][1]);
        acc[0][2] = fmaf(a0, w0.z, acc[0][2]); acc[0][3] = fmaf(a0, w0.w, acc[0][3]);
        acc[0][4] = fmaf(a0, w1.x, acc[0][4]); acc[0][5] = fmaf(a0, w1.y, acc[0][5]);
        acc[0][6] = fmaf(a0, w1.z, acc[0][6]); acc[0][7] = fmaf(a0, w1.w, acc[0][7]);
        acc[1][0] = fmaf(a1, w0.x, acc[1][0]); acc[1][1] = fmaf(a1, w0.y, acc[1][1]);
        acc[1][2] = fmaf(a1, w0.z, acc[1][2]); acc[1][3] = fmaf(a1, w0.w, acc[1][3]);
        acc[1][4] = fmaf(a1, w1.x, acc[1][4]); acc[1][5] = fmaf(a1, w1.y, acc[1][5]);
        acc[1][6] = fmaf(a1, w1.z, acc[1][6]); acc[1][7] = fmaf(a1, w1.w, acc[1][7]);
        acc[2][0] = fmaf(a2, w0.x, acc[2][0]); acc[2][1] = fmaf(a2, w0.y, acc[2][1]);
        acc[2][2] = fmaf(a2, w0.z, acc[2][2]); acc[2][3] = fmaf(a2, w0.w, acc[2][3]);
        acc[2][4] = fmaf(a2, w1.x, acc[2][4]); acc[2][5] = fmaf(a2, w1.y, acc[2][5]);
        acc[2][6] = fmaf(a2, w1.z, acc[2][6]); acc[2][7] = fmaf(a2, w1.w, acc[2][7]);
        acc[3][0] = fmaf(a3, w0.x, acc[3][0]); acc[3][1] = fmaf(a3, w0.y, acc[3][1]);
        acc[3][2] = fmaf(a3, w0.z, acc[3][2]); acc[3][3] = fmaf(a3, w0.w, acc[3][3]);
        acc[3][4] = fmaf(a3, w1.x, acc[3][4]); acc[3][5] = fmaf(a3, w1.y, acc[3][5]);
        acc[3][6] = fmaf(a3, w1.z, acc[3][6]); acc[3][7] = fmaf(a3, w1.w, acc[3][7]);
    }

    float bl[8];
    #pragma unroll
    for (int i = 0; i < 8; i++) bl[i] = __ldg(&b1[c0 + i]);

    #pragma unroll
    for (int jj = 0; jj < 4; jj++) {
        int n = n0 + j0 + jj;
        if (n < NN) {
            float4 r0, r1;
            r0.x = fmaxf(acc[jj][0] + bl[0], 0.f);
            r0.y = fmaxf(acc[jj][1] + bl[1], 0.f);
            r0.z = fmaxf(acc[jj][2] + bl[2], 0.f);
            r0.w = fmaxf(acc[jj][3] + bl[3], 0.f);
            r1.x = fmaxf(acc[jj][4] + bl[4], 0.f);
            r1.y = fmaxf(acc[jj][5] + bl[5], 0.f);
            r1.z = fmaxf(acc[jj][6] + bl[6], 0.f);
            r1.w = fmaxf(acc[jj][7] + bl[7], 0.f);
            *(float4*)&g_a1[n * F1 + c0]     = r0;
            *(float4*)&g_a1[n * F1 + c0 + 4] = r1;
        }
    }
}

// ---------------- GEMM2: h2 = a1 @ W2  (N x 128 @ 128 x 32) -----------------
__global__ void __launch_bounds__(128) k_gemm2(const float* __restrict__ W2) {
    __shared__ float sW[F1 * F2];        // 16 KB
    __shared__ float sA[F1 * 36];        // 18 KB
    int tid = threadIdx.x;
    int n0 = blockIdx.x * 32;

    {
        const float4* Wp = (const float4*)W2;
        float4* Sp = (float4*)sW;
        #pragma unroll
        for (int i = tid; i < F1 * F2 / 4; i += 128) Sp[i] = Wp[i];
    }
    for (int idx = tid; idx < 32 * F1; idx += 128) {
        int j = idx >> 7, k = idx & 127;
        sA[k * 36 + j] = (n0 + j < NN) ? g_a1[(n0 + j) * F1 + k] : 0.f;
    }
    __syncthreads();

    int cg = tid & 7, jg = tid >> 3;
    int c0 = cg * 4, j0 = jg * 2;

    float acc[2][4];
    #pragma unroll
    for (int a = 0; a < 2; a++)
        #pragma unroll
        for (int b = 0; b < 4; b++) acc[a][b] = 0.f;

    #pragma unroll 8
    for (int k = 0; k < F1; k++) {
        float4 w = *(const float4*)&sW[k * F2 + c0];
        float2 av = *(const float2*)&sA[k * 36 + j0];
        acc[0][0] = fmaf(av.x, w.x, acc[0][0]);
        acc[0][1] = fmaf(av.x, w.y, acc[0][1]);
        acc[0][2] = fmaf(av.x, w.z, acc[0][2]);
        acc[0][3] = fmaf(av.x, w.w, acc[0][3]);
        acc[1][0] = fmaf(av.y, w.x, acc[1][0]);
        acc[1][1] = fmaf(av.y, w.y, acc[1][1]);
        acc[1][2] = fmaf(av.y, w.z, acc[1][2]);
        acc[1][3] = fmaf(av.y, w.w, acc[1][3]);
    }

    #pragma unroll
    for (int jj = 0; jj < 2; jj++) {
        int n = n0 + j0 + jj;
        if (n < NN) {
            float4 r;
            r.x = acc[jj][0]; r.y = acc[jj][1]; r.z = acc[jj][2]; r.w = acc[jj][3];
            *(float4*)&g_h2[n * F2 + c0] = r;
        }
    }
}

// ------- Fused agg2 + classifier: h = agg(h2)+b2 ; out = h @ Wc + bc --------
__global__ void __launch_bounds__(256) k_agg2g3(const float* __restrict__ b2,
                                                const float* __restrict__ Wc,
                                                const float* __restrict__ bc,
                                                float* __restrict__ out,
                                                float* __restrict__ hout) {
    __shared__ float sW[F2 * F2];        // Wc, 4 KB, [k][c]
    int tid = threadIdx.x;
    for (int i = tid; i < F2 * F2; i += 256) sW[i] = Wc[i];
    __syncthreads();

    int gtid = blockIdx.x * 256 + tid;
    int n = gtid >> 5;
    int lane = gtid & 31;
    if (n >= NN) return;

    float dn = g_dinv[n];
    float acc = dn * g_h2[n * F2 + lane];

    int e = g_rowptr[n], end = g_rowptr[n + 1];
    for (; e + 3 < end; e += 4) {
        int s0 = g_colsrc[e], s1 = g_colsrc[e + 1], s2 = g_colsrc[e + 2], s3 = g_colsrc[e + 3];
        float d0 = g_dinv[s0], d1 = g_dinv[s1], d2 = g_dinv[s2], d3 = g_dinv[s3];
        acc += d0 * g_h2[s0 * F2 + lane] + d1 * g_h2[s1 * F2 + lane]
             + d2 * g_h2[s2 * F2 + lane] + d3 * g_h2[s3 * F2 + lane];
    }
    for (; e < end; e++) {
        int s = g_colsrc[e];
        acc += g_dinv[s] * g_h2[s * F2 + lane];
    }

    float h = dn * acc + b2[lane];
    hout[n * F2 + lane] = h;

    // out[n][lane] = sum_k h[k] * Wc[k][lane] + bc[lane]
    float o = 0.f;
    #pragma unroll
    for (int k = 0; k < F2; k++) {
        float hk = __shfl_sync(0xFFFFFFFFu, h, k);
        o = fmaf(hk, sW[k * F2 + lane], o);
    }
    out[n * F2 + lane] = o + bc[lane];
}

// ---------------- launch -----------------------------------------------------
extern "C" void kernel_launch(void* const* d_in, const int* in_sizes, int n_in,
                              void* d_out, int out_size) {
    const float* x   = (const float*)d_in[0];
    const int*   ei  = (const int*)d_in[1];
    const float* W1  = (const float*)d_in[2];
    const float* b1  = (const float*)d_in[3];
    const float* W2  = (const float*)d_in[4];
    const float* b2  = (const float*)d_in[5];
    const float* Wc  = (const float*)d_in[6];
    const float* bc  = (const float*)d_in[7];

    const int* src = ei;
    const int* dst = ei + NE;

    float* out  = (float*)d_out;            // [NN, F2]
    float* hout = (float*)d_out + NN * F2;  // [NN, F2]

    int nb_edges = (NE + 255) / 256;
    int nb_gemm  = (NN + 31) / 32;

    // CSR build (g_cnt is zero at entry: static init on first call,
    // self-zeroed by k_scan on every subsequent replay)
    k_count<<<nb_edges, 256>>>(dst);
    k_scan<<<1, 1024>>>();
    k_scatter<<<nb_edges, 256>>>(src, dst);

    // Layer 1 (reordered: aggregate x, then GEMM)
    k_aggx<<<(NN * 32 + 255) / 256, 256>>>(x);
    k_gemm1<<<nb_gemm, 128>>>(W1, b1);

    // Layer 2
    k_gemm2<<<nb_gemm, 128>>>(W2);

    // agg2 + classifier fused
    k_agg2g3<<<(NN * 32 + 255) / 256, 256>>>(b2, Wc, bc, out, hout);
}

// round 6
// speedup vs baseline: 1.8007x; 1.8007x over previous
#include <cuda_runtime.h>
#include <cuda_bf16.h>
#include <math.h>

#define NN      50000
#define NE      800000
#define F0      64
#define F1      128
#define F2      32
#define SCAN_B  1024
#define NBLK    ((NN + SCAN_B - 1) / SCAN_B)   // 49

// ---------------- scratch (static device globals) ----------------------------
__device__ float g_ax[NN * F0];     // aggregated x
__device__ float g_a1[NN * F1];     // relu(agg(x) @ W1 + b1)
__device__ float g_h2[NN * F2];     // a1 @ W2
__device__ float g_dinv[NN];
__device__ int   g_cnt[NN];
__device__ int   g_fill[NN];
__device__ int   g_rowptr[NN + 1];
__device__ int   g_blksum[64];
__device__ int   g_colsrc[NE];

// ---------------- CSR build --------------------------------------------------
__global__ void k_init() {
    int i = blockIdx.x * blockDim.x + threadIdx.x;
    if (i < NN) g_cnt[i] = 0;
}

__global__ void k_count(const int* __restrict__ dst) {
    int e = blockIdx.x * blockDim.x + threadIdx.x;
    if (e < NE) atomicAdd(&g_cnt[dst[e]], 1);
}

__global__ void k_scan1() {
    __shared__ int s[SCAN_B];
    int tid = threadIdx.x;
    int i = blockIdx.x * SCAN_B + tid;
    int v = (i < NN) ? g_cnt[i] : 0;
    if (i < NN) g_dinv[i] = rsqrtf((float)(v + 1));   // +1 self loop
    s[tid] = v;
    __syncthreads();
    #pragma unroll
    for (int off = 1; off < SCAN_B; off <<= 1) {
        int t = (tid >= off) ? s[tid - off] : 0;
        __syncthreads();
        s[tid] += t;
        __syncthreads();
    }
    if (i < NN) g_rowptr[i] = s[tid] - v;
    if (tid == SCAN_B - 1) g_blksum[blockIdx.x] = s[tid];
}

// 64-thread exclusive scan over NBLK=49 block sums (was single-thread serial)
__global__ void k_scan2() {
    __shared__ int s[64];
    int t = threadIdx.x;
    int v = (t < NBLK) ? g_blksum[t] : 0;
    s[t] = v;
    __syncthreads();
    #pragma unroll
    for (int off = 1; off < 64; off <<= 1) {
        int u = (t >= off) ? s[t - off] : 0;
        __syncthreads();
        s[t] += u;
        __syncthreads();
    }
    if (t < NBLK) g_blksum[t] = s[t] - v;   // exclusive
}

__global__ void k_scan3() {
    int i = blockIdx.x * blockDim.x + threadIdx.x;
    if (i < NN) {
        int r = g_rowptr[i] + g_blksum[i >> 10];
        g_rowptr[i] = r;
        g_fill[i] = r;
    }
    if (i == 0) g_rowptr[NN] = NE;
}

__global__ void k_scatter(const int* __restrict__ src, const int* __restrict__ dst) {
    int e = blockIdx.x * blockDim.x + threadIdx.x;
    if (e < NE) {
        int pos = atomicAdd(&g_fill[dst[e]], 1);
        g_colsrc[pos] = src[e];
    }
}

// ---------------- Aggregate x (F=64, warp per node, float2, unroll 8) --------
__global__ void __launch_bounds__(256) k_aggx(const float* __restrict__ x) {
    int gtid = blockIdx.x * blockDim.x + threadIdx.x;
    int n = gtid >> 5;
    int lane = gtid & 31;
    if (n >= NN) return;

    const float2* X = (const float2*)x;     // row = 32 float2
    float dn = g_dinv[n];
    float2 s = X[n * 32 + lane];
    float ax = dn * s.x, ay = dn * s.y;

    int e = g_rowptr[n], end = g_rowptr[n + 1];
    for (; e + 7 < end; e += 8) {
        int si[8];
        #pragma unroll
        for (int u = 0; u < 8; u++) si[u] = g_colsrc[e + u];
        float dv[8];
        #pragma unroll
        for (int u = 0; u < 8; u++) dv[u] = g_dinv[si[u]];
        float2 vv[8];
        #pragma unroll
        for (int u = 0; u < 8; u++) vv[u] = X[si[u] * 32 + lane];
        #pragma unroll
        for (int u = 0; u < 8; u++) {
            ax = fmaf(dv[u], vv[u].x, ax);
            ay = fmaf(dv[u], vv[u].y, ay);
        }
    }
    for (; e < end; e++) {
        int sc = g_colsrc[e];
        float d = g_dinv[sc];
        float2 v = X[sc * 32 + lane];
        ax = fmaf(d, v.x, ax);
        ay = fmaf(d, v.y, ay);
    }
    float2 o; o.x = dn * ax; o.y = dn * ay;
    ((float2*)g_ax)[n * 32 + lane] = o;
}

// ---------------- GEMM1: a1 = relu(agg_x @ W1 + b1)  (N x 64 @ 64 x 128) ----
__global__ void __launch_bounds__(128) k_gemm1(const float* __restrict__ W1,
                                               const float* __restrict__ b1) {
    __shared__ float sW[F0 * F1];        // 32 KB
    __shared__ float sA[F0 * 36];        // 9 KB, k-major, padded
    int tid = threadIdx.x;
    int n0 = blockIdx.x * 32;

    {
        const float4* Wp = (const float4*)W1;
        float4* Sp = (float4*)sW;
        #pragma unroll
        for (int i = tid; i < F0 * F1 / 4; i += 128) Sp[i] = Wp[i];
    }
    for (int idx = tid; idx < 32 * F0; idx += 128) {
        int j = idx >> 6, k = idx & 63;
        sA[k * 36 + j] = (n0 + j < NN) ? g_ax[(n0 + j) * F0 + k] : 0.f;
    }
    __syncthreads();

    int cg = tid & 15, jg = tid >> 4;
    int c0 = cg * 8, j0 = jg * 4;

    float acc[4][8];
    #pragma unroll
    for (int a = 0; a < 4; a++)
        #pragma unroll
        for (int b = 0; b < 8; b++) acc[a][b] = 0.f;

    #pragma unroll 4
    for (int k = 0; k < F0; k++) {
        float4 w0 = *(const float4*)&sW[k * F1 + c0];
        float4 w1 = *(const float4*)&sW[k * F1 + c0 + 4];
        float4 av = *(const float4*)&sA[k * 36 + j0];
        float a0 = av.x, a1 = av.y, a2 = av.z, a3 = av.w;
        acc[0][0] = fmaf(a0, w0.x, acc[0][0]); acc[0][1] = fmaf(a0, w0.y, acc[0][1]);
        acc[0][2] = fmaf(a0, w0.z, acc[0][2]); acc[0][3] = fmaf(a0, w0.w, acc[0][3]);
        acc[0][4] = fmaf(a0, w1.x, acc[0][4]); acc[0][5] = fmaf(a0, w1.y, acc[0][5]);
        acc[0][6] = fmaf(a0, w1.z, acc[0][6]); acc[0][7] = fmaf(a0, w1.w, acc[0][7]);
        acc[1][0] = fmaf(a1, w0.x, acc[1][0]); acc[1][1] = fmaf(a1, w0.y, acc[1][1]);
        acc[1][2] = fmaf(a1, w0.z, acc[1][2]); acc[1][3] = fmaf(a1, w0.w, acc[1][3]);
        acc[1][4] = fmaf(a1, w1.x, acc[1][4]); acc[1][5] = fmaf(a1, w1.y, acc[1][5]);
        acc[1][6] = fmaf(a1, w1.z, acc[1][6]); acc[1][7] = fmaf(a1, w1.w, acc[1][7]);
        acc[2][0] = fmaf(a2, w0.x, acc[2][0]); acc[2][1] = fmaf(a2, w0.y, acc[2][1]);
        acc[2][2] = fmaf(a2, w0.z, acc[2][2]); acc[2][3] = fmaf(a2, w0.w, acc[2][3]);
        acc[2][4] = fmaf(a2, w1.x, acc[2][4]); acc[2][5] = fmaf(a2, w1.y, acc[2][5]);
        acc[2][6] = fmaf(a2, w1.z, acc[2][6]); acc[2][7] = fmaf(a2, w1.w, acc[2][7]);
        acc[3][0] = fmaf(a3, w0.x, acc[3][0]); acc[3][1] = fmaf(a3, w0.y, acc[3][1]);
        acc[3][2] = fmaf(a3, w0.z, acc[3][2]); acc[3][3] = fmaf(a3, w0.w, acc[3][3]);
        acc[3][4] = fmaf(a3, w1.x, acc[3][4]); acc[3][5] = fmaf(a3, w1.y, acc[3][5]);
        acc[3][6] = fmaf(a3, w1.z, acc[3][6]); acc[3][7] = fmaf(a3, w1.w, acc[3][7]);
    }

    float bl[8];
    #pragma unroll
    for (int i = 0; i < 8; i++) bl[i] = __ldg(&b1[c0 + i]);

    #pragma unroll
    for (int jj = 0; jj < 4; jj++) {
        int n = n0 + j0 + jj;
        if (n < NN) {
            float4 r0, r1;
            r0.x = fmaxf(acc[jj][0] + bl[0], 0.f);
            r0.y = fmaxf(acc[jj][1] + bl[1], 0.f);
            r0.z = fmaxf(acc[jj][2] + bl[2], 0.f);
            r0.w = fmaxf(acc[jj][3] + bl[3], 0.f);
            r1.x = fmaxf(acc[jj][4] + bl[4], 0.f);
            r1.y = fmaxf(acc[jj][5] + bl[5], 0.f);
            r1.z = fmaxf(acc[jj][6] + bl[6], 0.f);
            r1.w = fmaxf(acc[jj][7] + bl[7], 0.f);
            *(float4*)&g_a1[n * F1 + c0]     = r0;
            *(float4*)&g_a1[n * F1 + c0 + 4] = r1;
        }
    }
}

// ---------------- GEMM2: h2 = a1 @ W2  (N x 128 @ 128 x 32) -----------------
__global__ void __launch_bounds__(128) k_gemm2(const float* __restrict__ W2) {
    __shared__ float sW[F1 * F2];        // 16 KB
    __shared__ float sA[F1 * 36];        // 18 KB
    int tid = threadIdx.x;
    int n0 = blockIdx.x * 32;

    {
        const float4* Wp = (const float4*)W2;
        float4* Sp = (float4*)sW;
        #pragma unroll
        for (int i = tid; i < F1 * F2 / 4; i += 128) Sp[i] = Wp[i];
    }
    for (int idx = tid; idx < 32 * F1; idx += 128) {
        int j = idx >> 7, k = idx & 127;
        sA[k * 36 + j] = (n0 + j < NN) ? g_a1[(n0 + j) * F1 + k] : 0.f;
    }
    __syncthreads();

    int cg = tid & 7, jg = tid >> 3;
    int c0 = cg * 4, j0 = jg * 2;

    float acc[2][4];
    #pragma unroll
    for (int a = 0; a < 2; a++)
        #pragma unroll
        for (int b = 0; b < 4; b++) acc[a][b] = 0.f;

    #pragma unroll 8
    for (int k = 0; k < F1; k++) {
        float4 w = *(const float4*)&sW[k * F2 + c0];
        float2 av = *(const float2*)&sA[k * 36 + j0];
        acc[0][0] = fmaf(av.x, w.x, acc[0][0]);
        acc[0][1] = fmaf(av.x, w.y, acc[0][1]);
        acc[0][2] = fmaf(av.x, w.z, acc[0][2]);
        acc[0][3] = fmaf(av.x, w.w, acc[0][3]);
        acc[1][0] = fmaf(av.y, w.x, acc[1][0]);
        acc[1][1] = fmaf(av.y, w.y, acc[1][1]);
        acc[1][2] = fmaf(av.y, w.z, acc[1][2]);
        acc[1][3] = fmaf(av.y, w.w, acc[1][3]);
    }

    #pragma unroll
    for (int jj = 0; jj < 2; jj++) {
        int n = n0 + j0 + jj;
        if (n < NN) {
            float4 r;
            r.x = acc[jj][0]; r.y = acc[jj][1]; r.z = acc[jj][2]; r.w = acc[jj][3];
            *(float4*)&g_h2[n * F2 + c0] = r;
        }
    }
}

// ------- Fused agg2 + classifier: h = agg(h2)+b2 ; out = h @ Wc + bc --------
__global__ void __launch_bounds__(256) k_agg2g3(const float* __restrict__ b2,
                                                const float* __restrict__ Wc,
                                                const float* __restrict__ bc,
                                                float* __restrict__ out,
                                                float* __restrict__ hout) {
    __shared__ float sW[F2 * F2];        // Wc, 4 KB, [k][c]
    int tid = threadIdx.x;
    for (int i = tid; i < F2 * F2; i += 256) sW[i] = Wc[i];
    __syncthreads();

    int gtid = blockIdx.x * 256 + tid;
    int n = gtid >> 5;
    int lane = gtid & 31;
    if (n >= NN) return;

    float dn = g_dinv[n];
    float acc = dn * g_h2[n * F2 + lane];

    int e = g_rowptr[n], end = g_rowptr[n + 1];
    for (; e + 3 < end; e += 4) {
        int s0 = g_colsrc[e], s1 = g_colsrc[e + 1], s2 = g_colsrc[e + 2], s3 = g_colsrc[e + 3];
        float d0 = g_dinv[s0], d1 = g_dinv[s1], d2 = g_dinv[s2], d3 = g_dinv[s3];
        acc += d0 * g_h2[s0 * F2 + lane] + d1 * g_h2[s1 * F2 + lane]
             + d2 * g_h2[s2 * F2 + lane] + d3 * g_h2[s3 * F2 + lane];
    }
    for (; e < end; e++) {
        int s = g_colsrc[e];
        acc += g_dinv[s] * g_h2[s * F2 + lane];
    }

    float h = dn * acc + b2[lane];
    hout[n * F2 + lane] = h;

    // out[n][lane] = sum_k h[k] * Wc[k][lane] + bc[lane]
    float o = 0.f;
    #pragma unroll
    for (int k = 0; k < F2; k++) {
        float hk = __shfl_sync(0xFFFFFFFFu, h, k);
        o = fmaf(hk, sW[k * F2 + lane], o);
    }
    out[n * F2 + lane] = o + bc[lane];
}

// ---------------- launch -----------------------------------------------------
extern "C" void kernel_launch(void* const* d_in, const int* in_sizes, int n_in,
                              void* d_out, int out_size) {
    const float* x   = (const float*)d_in[0];
    const int*   ei  = (const int*)d_in[1];
    const float* W1  = (const float*)d_in[2];
    const float* b1  = (const float*)d_in[3];
    const float* W2  = (const float*)d_in[4];
    const float* b2  = (const float*)d_in[5];
    const float* Wc  = (const float*)d_in[6];
    const float* bc  = (const float*)d_in[7];

    const int* src = ei;
    const int* dst = ei + NE;

    float* out  = (float*)d_out;            // [NN, F2]
    float* hout = (float*)d_out + NN * F2;  // [NN, F2]

    int nb_nodes = (NN + 255) / 256;
    int nb_edges = (NE + 255) / 256;
    int nb_gemm  = (NN + 31) / 32;

    // CSR build
    k_init<<<nb_nodes, 256>>>();
    k_count<<<nb_edges, 256>>>(dst);
    k_scan1<<<NBLK, SCAN_B>>>();
    k_scan2<<<1, 64>>>();
    k_scan3<<<nb_nodes, 256>>>();
    k_scatter<<<nb_edges, 256>>>(src, dst);

    // Layer 1 (reordered: aggregate x, then GEMM)
    k_aggx<<<(NN * 32 + 255) / 256, 256>>>(x);
    k_gemm1<<<nb_gemm, 128>>>(W1, b1);

    // Layer 2
    k_gemm2<<<nb_gemm, 128>>>(W2);

    // agg2 + classifier fused
    k_agg2g3<<<(NN * 32 + 255) / 256, 256>>>(b2, Wc, bc, out, hout);
}